// round 14
// baseline (speedup 1.0000x reference)
#include <cuda_runtime.h>
#include <cstddef>
#include <cstdint>

#define BATCH 512
#define TT    512
#define DD    128
#define DOUTN 32
#define CCLS  4
#define TBK   32
#define NTILE (TT / TBK)
#define RP    33
#define PLP   25
#define PTP   68            // projT pitch (floats): conflict-free + 16B aligned

#define ALPHA_C 0.1f
#define GAMMA_C 0.9f
#define EPS_C   1e-5f
#define EPSH_C  1e-6f
#define LNEPS_C 1e-5f

__device__ __forceinline__ float warp_sum(float v) {
#pragma unroll
    for (int s = 16; s > 0; s >>= 1)
        v += __shfl_xor_sync(0xffffffffu, v, s, 32);
    return v;
}

__device__ __forceinline__ unsigned long long fma2(unsigned long long a,
                                                   unsigned long long b,
                                                   unsigned long long c) {
    unsigned long long d;
    asm("fma.rn.f32x2 %0, %1, %2, %3;" : "=l"(d) : "l"(a), "l"(b), "l"(c));
    return d;
}

__device__ __forceinline__ unsigned long long add2(unsigned long long a,
                                                   unsigned long long b) {
    unsigned long long d;
    asm("add.rn.f32x2 %0, %1, %2;" : "=l"(d) : "l"(a), "l"(b));
    return d;
}

__device__ __forceinline__ unsigned long long pack2(float lo, float hi) {
    unsigned long long r;
    asm("mov.b64 %0, {%1, %2};" : "=l"(r) : "f"(lo), "f"(hi));
    return r;
}

__device__ __forceinline__ void unpack2(unsigned long long v, float& lo, float& hi) {
    asm("mov.b64 {%0, %1}, %2;" : "=f"(lo), "=f"(hi) : "l"(v));
}

__device__ __forceinline__ uint32_t sm_u32(const void* p) {
    uint32_t a;
    asm("{ .reg .u64 t; cvta.to.shared.u64 t, %1; cvt.u32.u64 %0, t; }"
        : "=r"(a) : "l"(p));
    return a;
}

__device__ __forceinline__ void cpa16(uint32_t dst, const void* src) {
    asm volatile("cp.async.cg.shared.global [%0], [%1], 16;" :: "r"(dst), "l"(src));
}
__device__ __forceinline__ void cpa_commit() {
    asm volatile("cp.async.commit_group;");
}
__device__ __forceinline__ void cpa_wait1() {
    asm volatile("cp.async.wait_group 1;");
}
__device__ __forceinline__ void cpa_wait0() {
    asm volatile("cp.async.wait_group 0;");
}

__global__ __launch_bounds__(128, 3)
void sync_head_kernel(const float* __restrict__ z_ticks,
                      const float* __restrict__ proj,
                      const float* __restrict__ ln_w,
                      const float* __restrict__ ln_b,
                      const float* __restrict__ cls_w,
                      const float* __restrict__ cls_b,
                      float* __restrict__ out_x,
                      float* __restrict__ out_logits) {
    __shared__ __align__(16) float smz[2][TBK * DD];
    __shared__ __align__(16) float smM2[TBK * DD];
    __shared__ float smr[TBK * RP];
    __shared__ float pci[TBK], pcy[TBK], pcz[TBK], pcw[TBK];
    __shared__ float pl[TBK * PLP];
    __shared__ __align__(16) float A[DOUTN][CCLS];
    __shared__ __align__(16) float projT[DOUTN * PTP];   // [j][d-64]
    __shared__ float4 SaV, SbV;

    const int tid  = threadIdx.x;
    const int lane = tid & 31;
    const int w    = tid >> 5;
    const int b    = blockIdx.x;

    // ---- folded LN x classifier constants ----
    {
        int j = tid >> 2, c = tid & 3;
        A[j][c] = ln_w[j] * cls_w[c * DOUTN + j];
    }
    if (tid < 2 * CCLS) {
        int c = tid & 3;
        float acc = 0.f;
        if (tid < CCLS) {
            for (int j = 0; j < DOUTN; j++) acc += ln_w[j] * cls_w[c * DOUTN + j];
            ((float*)&SaV)[c] = acc;
        } else {
            for (int j = 0; j < DOUTN; j++) acc += ln_b[j] * cls_w[c * DOUTN + j];
            ((float*)&SbV)[c] = acc + cls_b[c];
        }
    }

    // ---- upper half of proj transposed to smem: projT[j][dh] = proj[64+dh][j] ----
    for (int i = tid; i < DOUTN * 64; i += 128) {
        const int j  = i & 31;
        const int dh = i >> 5;
        projT[j * PTP + dh] = proj[(64 + dh) * DOUTN + j];
    }

    // ---- lower half of proj column `lane` in registers (d = 0..63) ----
    unsigned long long q[32];
#pragma unroll
    for (int i = 0; i < 32; i++) {
        float a  = proj[(2 * i) * DOUTN + lane];
        float bb = proj[(2 * i + 1) * DOUTN + lane];
        q[i] = pack2(a, bb);
    }

    const float4* zg4 = (const float4*)(z_ticks + (size_t)b * TT * DD);
    float* oxb  = out_x + (size_t)b * TT * DOUTN;
    float4* olb = (float4*)(out_logits + (size_t)b * TT * CCLS);

    const float gmn = __powf(GAMMA_C, -(float)lane);
    const float gpp = __powf(GAMMA_C,  (float)lane);

    // ---- prefetch tile 0 ----
    {
        const uint32_t dst0 = sm_u32(&smz[0][0]);
#pragma unroll
        for (int k = 0; k < 8; k++)
            cpa16(dst0 + (tid + 128 * k) * 16, zg4 + tid + 128 * k);
        cpa_commit();
    }
    __syncthreads();
    const float4 Sa4 = SaV;
    const float4 Sb4 = SbV;

    float S1c = 0.f, S2c = 0.f;
    float hc[8];
#pragma unroll
    for (int i = 0; i < 8; i++) hc[i] = 0.f;

#pragma unroll 1
    for (int tile = 0; tile < NTILE; tile++) {
        const int tb  = tile * TBK;
        const int cur = tile & 1;
        const int nxt = cur ^ 1;

        if (tid < TBK) {
            const float tau   = (float)(tb + tid + 1);
            const float denom = fmaxf(tau - 1.0f, 1.0f);
            const float idn   = 1.0f / denom;
            pci[tid] = 1.0f / tau;
            pcy[tid] = (1.0f - ALPHA_C) * idn;
            pcz[tid] = ALPHA_C * idn * (1.0f / 128.0f);
            pcw[tid] = (1.0f - GAMMA_C) / (1.0f - __powf(GAMMA_C, tau));
        }

        if (tile + 1 < NTILE) {
            const uint32_t dstn = sm_u32(&smz[nxt][0]);
            const float4* src = zg4 + (size_t)(tb + TBK) * (DD / 4);
#pragma unroll
            for (int k = 0; k < 8; k++)
                cpa16(dstn + (tid + 128 * k) * 16, src + tid + 128 * k);
            cpa_commit();
            cpa_wait1();
        } else {
            cpa_wait0();
        }
        __syncthreads();      // B1

        // ---- phase 2: prefix scan over t for dim d = tid ----
        {
            float* zc = smz[cur];
#pragma unroll
            for (int t = 0; t < TBK; t++) {
                const float zz = zc[t * DD + tid];
                S1c += zz;
                S2c = fmaf(zz, zz, S2c);
                const float m   = S1c * pci[t];
                zc[t * DD + tid]   = zz - m;
                smM2[t * DD + tid] = fmaf(-m, S1c, S2c);
            }
        }
        __syncthreads();      // B2

        // ---- phases 3-5 (warp-local rows t = 8w..8w+7) ----
        {
            float c2v[8], c1v[8];
#pragma unroll
            for (int k = 0; k < 8; k++) {
                const int t = w * 8 + k;
                const float* row = smM2 + t * DD;
                float v = (row[lane] + row[lane + 32]) +
                          (row[lane + 64] + row[lane + 96]);
                v = warp_sum(v);
                c2v[k] = fmaf(v, pcz[t], EPS_C);
                c1v[k] = pcy[t];
            }
#pragma unroll
            for (int k = 0; k < 8; k++) {
                const int t = w * 8 + k;
                float4* zrow  = (float4*)(smz[cur] + t * DD);
                float4* m2row = (float4*)(smM2 + t * DD);
                float4 nm = zrow[lane];
                float4 m2 = m2row[lane];
                float4 zt;
                zt.x = nm.x * rsqrtf(fmaf(m2.x, c1v[k], c2v[k]));
                zt.y = nm.y * rsqrtf(fmaf(m2.y, c1v[k], c2v[k]));
                zt.z = nm.z * rsqrtf(fmaf(m2.z, c1v[k], c2v[k]));
                zt.w = nm.w * rsqrtf(fmaf(m2.w, c1v[k], c2v[k]));
                zrow[lane] = zt;
            }
            __syncwarp();
            const ulonglong2* pj = (const ulonglong2*)(projT + lane * PTP);
#pragma unroll
            for (int k = 0; k < 8; k++) {
                const int t = w * 8 + k;
                const ulonglong2* zp = (const ulonglong2*)(smz[cur] + t * DD);
                unsigned long long a0 = 0ull, a1 = 0ull, a2 = 0ull, a3 = 0ull;
                // d = 0..63 via register q
#pragma unroll
                for (int c = 0; c < 8; c++) {
                    ulonglong2 za = zp[2 * c];
                    ulonglong2 zc = zp[2 * c + 1];
                    a0 = fma2(za.x, q[4 * c + 0], a0);
                    a1 = fma2(za.y, q[4 * c + 1], a1);
                    a2 = fma2(zc.x, q[4 * c + 2], a2);
                    a3 = fma2(zc.y, q[4 * c + 3], a3);
                }
                // d = 64..127 via smem projT (per-lane row, conflict-free)
#pragma unroll
                for (int c = 0; c < 8; c++) {
                    ulonglong2 za = zp[16 + 2 * c];
                    ulonglong2 zc = zp[16 + 2 * c + 1];
                    ulonglong2 pa = pj[2 * c];
                    ulonglong2 pc = pj[2 * c + 1];
                    a0 = fma2(za.x, pa.x, a0);
                    a1 = fma2(za.y, pa.y, a1);
                    a2 = fma2(zc.x, pc.x, a2);
                    a3 = fma2(zc.y, pc.y, a3);
                }
                unsigned long long sT = add2(add2(a0, a1), add2(a2, a3));
                float rlo, rhi;
                unpack2(sT, rlo, rhi);
                smr[t * RP + lane] = rlo + rhi;
            }
        }
        __syncthreads();      // B3

        // ---- phase 6+7a: parallel h-scan (lane = t) + LN partials ----
        {
            const float invs = pcw[lane];
            float sx = 0.f, sx2 = 0.f;
            float d0 = 0.f, d1 = 0.f, d2 = 0.f, d3 = 0.f;
#pragma unroll
            for (int i = 0; i < 8; i++) {
                const int j = w * 8 + i;
                const float r = smr[lane * RP + j];
                float pf = r * r * gmn;
#pragma unroll
                for (int s = 1; s < 32; s <<= 1) {
                    float o = __shfl_up_sync(0xffffffffu, pf, s, 32);
                    if (lane >= s) pf += o;
                }
                const float h = gpp * fmaf(GAMMA_C, hc[i], pf);
                hc[i] = __shfl_sync(0xffffffffu, h, 31, 32);
                const float x = __logf(fmaf(h, invs, EPSH_C));
                smr[lane * RP + j] = x;
                const float4 Aj = *(const float4*)&A[j][0];
                sx  += x;
                sx2 = fmaf(x, x, sx2);
                d0 = fmaf(x, Aj.x, d0);
                d1 = fmaf(x, Aj.y, d1);
                d2 = fmaf(x, Aj.z, d2);
                d3 = fmaf(x, Aj.w, d3);
            }
            float* p = pl + lane * PLP + w * 6;
            p[0] = sx;  p[1] = sx2;
            p[2] = d0;  p[3] = d1;  p[4] = d2;  p[5] = d3;
        }
        __syncthreads();      // B4

        // ---- phase 7b: x store + LN finish ----
        {
#pragma unroll
            for (int it = 0; it < 2; it++) {
                const int g  = tid + 128 * it;
                const int t  = g >> 3;
                const int j0 = (g & 7) * 4;
                float4 v;
                v.x = smr[t * RP + j0 + 0];
                v.y = smr[t * RP + j0 + 1];
                v.z = smr[t * RP + j0 + 2];
                v.w = smr[t * RP + j0 + 3];
                ((float4*)(oxb + (size_t)(tb + t) * DOUTN))[g & 7] = v;
            }
        }
        if (tid < TBK) {
            const int t = tid;
            float sx = 0.f, sx2 = 0.f, d0 = 0.f, d1 = 0.f, d2 = 0.f, d3 = 0.f;
#pragma unroll
            for (int w2 = 0; w2 < 4; w2++) {
                const float* p = pl + t * PLP + w2 * 6;
                sx  += p[0];  sx2 += p[1];
                d0  += p[2];  d1  += p[3];
                d2  += p[4];  d3  += p[5];
            }
            const float mu      = sx * (1.0f / 32.0f);
            const float var     = fmaxf(fmaf(sx2, 1.0f / 32.0f, -mu * mu), 0.0f);
            const float inv_std = rsqrtf(var + LNEPS_C);
            float4 lg;
            lg.x = fmaf(inv_std, fmaf(-mu, Sa4.x, d0), Sb4.x);
            lg.y = fmaf(inv_std, fmaf(-mu, Sa4.y, d1), Sb4.y);
            lg.z = fmaf(inv_std, fmaf(-mu, Sa4.z, d2), Sb4.z);
            lg.w = fmaf(inv_std, fmaf(-mu, Sa4.w, d3), Sb4.w);
            olb[tb + t] = lg;
        }
    }
}

extern "C" void kernel_launch(void* const* d_in, const int* in_sizes, int n_in,
                              void* d_out, int out_size) {
    const float* z_ticks = (const float*)d_in[0];
    const float* proj    = (const float*)d_in[1];
    const float* ln_w    = (const float*)d_in[2];
    const float* ln_b    = (const float*)d_in[3];
    const float* cls_w   = (const float*)d_in[4];
    const float* cls_b   = (const float*)d_in[5];

    float* out_x      = (float*)d_out;
    float* out_logits = out_x + (size_t)BATCH * TT * DOUTN;

    sync_head_kernel<<<BATCH, 128>>>(z_ticks, proj, ln_w, ln_b,
                                     cls_w, cls_b, out_x, out_logits);
}

// round 15
// speedup vs baseline: 1.3091x; 1.3091x over previous
#include <cuda_runtime.h>
#include <cstddef>
#include <cstdint>

#define BATCH 512
#define TT    512
#define DD    128
#define DOUTN 32
#define CCLS  4
#define TBK   32
#define NTILE (TT / TBK)      // 16
#define RP    33
#define PLP   25
#define GRID  296             // 2 CTAs x 148 SMs, single wave

#define ALPHA_C 0.1f
#define GAMMA_C 0.9f
#define EPS_C   1e-5f
#define EPSH_C  1e-6f
#define LNEPS_C 1e-5f

__device__ __forceinline__ float warp_sum(float v) {
#pragma unroll
    for (int s = 16; s > 0; s >>= 1)
        v += __shfl_xor_sync(0xffffffffu, v, s, 32);
    return v;
}

__device__ __forceinline__ unsigned long long fma2(unsigned long long a,
                                                   unsigned long long b,
                                                   unsigned long long c) {
    unsigned long long d;
    asm("fma.rn.f32x2 %0, %1, %2, %3;" : "=l"(d) : "l"(a), "l"(b), "l"(c));
    return d;
}

__device__ __forceinline__ unsigned long long add2(unsigned long long a,
                                                   unsigned long long b) {
    unsigned long long d;
    asm("add.rn.f32x2 %0, %1, %2;" : "=l"(d) : "l"(a), "l"(b));
    return d;
}

__device__ __forceinline__ unsigned long long pack2(float lo, float hi) {
    unsigned long long r;
    asm("mov.b64 %0, {%1, %2};" : "=l"(r) : "f"(lo), "f"(hi));
    return r;
}

__device__ __forceinline__ void unpack2(unsigned long long v, float& lo, float& hi) {
    asm("mov.b64 {%0, %1}, %2;" : "=f"(lo), "=f"(hi) : "l"(v));
}

__device__ __forceinline__ uint32_t sm_u32(const void* p) {
    uint32_t a;
    asm("{ .reg .u64 t; cvta.to.shared.u64 t, %1; cvt.u32.u64 %0, t; }"
        : "=r"(a) : "l"(p));
    return a;
}

__device__ __forceinline__ void cpa16(uint32_t dst, const void* src) {
    asm volatile("cp.async.cg.shared.global [%0], [%1], 16;" :: "r"(dst), "l"(src));
}
__device__ __forceinline__ void cpa_commit() {
    asm volatile("cp.async.commit_group;");
}
__device__ __forceinline__ void cpa_wait1() {
    asm volatile("cp.async.wait_group 1;");
}
__device__ __forceinline__ void cpa_wait0() {
    asm volatile("cp.async.wait_group 0;");
}

__global__ __launch_bounds__(128, 2)
void sync_head_kernel(const float* __restrict__ z_ticks,
                      const float* __restrict__ proj,
                      const float* __restrict__ ln_w,
                      const float* __restrict__ ln_b,
                      const float* __restrict__ cls_w,
                      const float* __restrict__ cls_b,
                      float* __restrict__ out_x,
                      float* __restrict__ out_logits) {
    __shared__ __align__(16) float  smz[2][TBK * DD];   // z -> z_tilde (dbl buf)
    __shared__ __align__(16) float2 smnm[TBK * DD];     // (num, M2) packed
    __shared__ float smr[TBK * RP];                     // r -> x
    __shared__ float pci[TBK], pcy[TBK], pcz[TBK], pcw[TBK];
    __shared__ float pl[TBK * PLP];                     // LN partials
    __shared__ __align__(16) float A[DOUTN][CCLS];
    __shared__ float4 SaV, SbV;

    const int tid  = threadIdx.x;
    const int lane = tid & 31;
    const int w    = tid >> 5;

    const int b0   = blockIdx.x;
    const int nbat = (b0 < BATCH - GRID) ? 2 : 1;
    const int ngt  = nbat * NTILE;

    // ---- folded LN x classifier constants ----
    {
        int j = tid >> 2, c = tid & 3;
        A[j][c] = ln_w[j] * cls_w[c * DOUTN + j];
    }
    if (tid < 2 * CCLS) {
        int c = tid & 3;
        float acc = 0.f;
        if (tid < CCLS) {
            for (int j = 0; j < DOUTN; j++) acc += ln_w[j] * cls_w[c * DOUTN + j];
            ((float*)&SaV)[c] = acc;
        } else {
            for (int j = 0; j < DOUTN; j++) acc += ln_b[j] * cls_w[c * DOUTN + j];
            ((float*)&SbV)[c] = acc + cls_b[c];
        }
    }

    // ---- proj column `lane` fully in registers ----
    unsigned long long q[DD / 2];
#pragma unroll
    for (int i = 0; i < DD / 2; i++) {
        float a  = proj[(2 * i) * DOUTN + lane];
        float bb = proj[(2 * i + 1) * DOUTN + lane];
        q[i] = pack2(a, bb);
    }

    const float gmn = __powf(GAMMA_C, -(float)lane);
    const float gpp = __powf(GAMMA_C,  (float)lane);

    // ---- prefetch gt = 0 (batch b0, tile 0) ----
    {
        const uint32_t dst0 = sm_u32(&smz[0][0]);
        const float4* src = (const float4*)(z_ticks + (size_t)b0 * TT * DD);
#pragma unroll
        for (int k = 0; k < 8; k++)
            cpa16(dst0 + (tid + 128 * k) * 16, src + tid + 128 * k);
        cpa_commit();
    }
    __syncthreads();
    const float4 Sa4 = SaV;
    const float4 Sb4 = SbV;

    float S1c = 0.f, S2c = 0.f;
    float hc[8];
#pragma unroll
    for (int i = 0; i < 8; i++) hc[i] = 0.f;

#pragma unroll 1
    for (int gt = 0; gt < ngt; gt++) {
        const int tile = gt & (NTILE - 1);
        const int tb   = tile * TBK;
        const int bat  = (gt < NTILE) ? b0 : (GRID + b0);
        const int cur  = gt & 1;
        const int nxt  = cur ^ 1;

        if (tile == 0) {
            S1c = 0.f;  S2c = 0.f;
#pragma unroll
            for (int i = 0; i < 8; i++) hc[i] = 0.f;
        }

        if (tid < TBK) {
            const float tau   = (float)(tb + tid + 1);
            const float denom = fmaxf(tau - 1.0f, 1.0f);
            const float idn   = 1.0f / denom;
            pci[tid] = 1.0f / tau;
            pcy[tid] = (1.0f - ALPHA_C) * idn;
            pcz[tid] = ALPHA_C * idn * (1.0f / 128.0f);
            pcw[tid] = (1.0f - GAMMA_C) / (1.0f - __powf(GAMMA_C, tau));
        }

        // prefetch next gt into the other buffer
        if (gt + 1 < ngt) {
            const int gn    = gt + 1;
            const int batn  = (gn < NTILE) ? b0 : (GRID + b0);
            const int tbn   = (gn & (NTILE - 1)) * TBK;
            const uint32_t dstn = sm_u32(&smz[nxt][0]);
            const float4* src = (const float4*)(z_ticks + (size_t)batn * TT * DD)
                                + (size_t)tbn * (DD / 4);
#pragma unroll
            for (int k = 0; k < 8; k++)
                cpa16(dstn + (tid + 128 * k) * 16, src + tid + 128 * k);
            cpa_commit();
            cpa_wait1();
        } else {
            cpa_wait0();
        }
        __syncthreads();      // B1

        // ---- phase 2: prefix scan over t for dim d = tid ----
        {
            const float* zc = smz[cur];
#pragma unroll
            for (int t = 0; t < TBK; t++) {
                const float zz = zc[t * DD + tid];
                S1c += zz;
                S2c = fmaf(zz, zz, S2c);
                const float m = S1c * pci[t];
                smnm[t * DD + tid] = make_float2(zz - m, fmaf(-m, S1c, S2c));
            }
        }
        __syncthreads();      // B2

        // ---- phases 3-5 (warp-local rows t = 8w..8w+7) ----
        {
            float c2v[8], c1v[8];
#pragma unroll
            for (int k = 0; k < 8; k++) {
                const int t = w * 8 + k;
                const float2* row = smnm + t * DD;
                float v = (row[lane].y + row[lane + 32].y) +
                          (row[lane + 64].y + row[lane + 96].y);
                v = warp_sum(v);
                c2v[k] = fmaf(v, pcz[t], EPS_C);
                c1v[k] = pcy[t];
            }
#pragma unroll
            for (int k = 0; k < 8; k++) {
                const int t = w * 8 + k;
                const float4* nm4 = (const float4*)(smnm + t * DD);
                float4 a  = nm4[2 * lane];        // (num,M2) x 2 : d = 4l,4l+1
                float4 b2 = nm4[2 * lane + 1];    // d = 4l+2,4l+3
                float4 zt;
                zt.x = a.x  * rsqrtf(fmaf(a.y,  c1v[k], c2v[k]));
                zt.y = a.z  * rsqrtf(fmaf(a.w,  c1v[k], c2v[k]));
                zt.z = b2.x * rsqrtf(fmaf(b2.y, c1v[k], c2v[k]));
                zt.w = b2.z * rsqrtf(fmaf(b2.w, c1v[k], c2v[k]));
                ((float4*)(smz[cur] + t * DD))[lane] = zt;
            }
            __syncwarp();
#pragma unroll
            for (int k = 0; k < 8; k++) {
                const int t = w * 8 + k;
                const ulonglong2* zp = (const ulonglong2*)(smz[cur] + t * DD);
                unsigned long long a0 = 0ull, a1 = 0ull, a2 = 0ull, a3 = 0ull;
#pragma unroll
                for (int c = 0; c < 16; c++) {
                    ulonglong2 za = zp[2 * c];
                    ulonglong2 zc = zp[2 * c + 1];
                    a0 = fma2(za.x, q[4 * c + 0], a0);
                    a1 = fma2(za.y, q[4 * c + 1], a1);
                    a2 = fma2(zc.x, q[4 * c + 2], a2);
                    a3 = fma2(zc.y, q[4 * c + 3], a3);
                }
                unsigned long long sT = add2(add2(a0, a1), add2(a2, a3));
                float rlo, rhi;
                unpack2(sT, rlo, rhi);
                smr[t * RP + lane] = rlo + rhi;
            }
        }
        __syncthreads();      // B3

        // ---- phase 6: parallel h prefix-scan (lane = t) + LN partials ----
        {
            const float invs = pcw[lane];
            float sx = 0.f, sx2 = 0.f;
            float d0 = 0.f, d1 = 0.f, d2 = 0.f, d3 = 0.f;
#pragma unroll
            for (int i = 0; i < 8; i++) {
                const int j = w * 8 + i;
                const float r = smr[lane * RP + j];
                float pf = r * r * gmn;
#pragma unroll
                for (int s = 1; s < 32; s <<= 1) {
                    float o = __shfl_up_sync(0xffffffffu, pf, s, 32);
                    if (lane >= s) pf += o;
                }
                const float h = gpp * fmaf(GAMMA_C, hc[i], pf);
                hc[i] = __shfl_sync(0xffffffffu, h, 31, 32);
                const float x = __logf(fmaf(h, invs, EPSH_C));
                smr[lane * RP + j] = x;
                const float4 Aj = *(const float4*)&A[j][0];
                sx  += x;
                sx2 = fmaf(x, x, sx2);
                d0 = fmaf(x, Aj.x, d0);
                d1 = fmaf(x, Aj.y, d1);
                d2 = fmaf(x, Aj.z, d2);
                d3 = fmaf(x, Aj.w, d3);
            }
            float* p = pl + lane * PLP + w * 6;
            p[0] = sx;  p[1] = sx2;
            p[2] = d0;  p[3] = d1;  p[4] = d2;  p[5] = d3;
        }
        __syncthreads();      // B4

        // ---- phase 7a: x store (all threads, coalesced STG.128) ----
        {
            float* oxt = out_x + ((size_t)bat * TT + tb) * DOUTN;
#pragma unroll
            for (int it = 0; it < 2; it++) {
                const int g  = tid + 128 * it;
                const int t  = g >> 3;
                const int j0 = (g & 7) * 4;
                float4 v;
                v.x = smr[t * RP + j0 + 0];
                v.y = smr[t * RP + j0 + 1];
                v.z = smr[t * RP + j0 + 2];
                v.w = smr[t * RP + j0 + 3];
                ((float4*)(oxt + (size_t)t * DOUTN))[g & 7] = v;
            }
        }
        // ---- phase 7b: LN finish, spread across warps (lane < 8) ----
        if (lane < 8) {
            const int t = w * 8 + lane;
            float sx = 0.f, sx2 = 0.f, d0 = 0.f, d1 = 0.f, d2 = 0.f, d3 = 0.f;
#pragma unroll
            for (int w2 = 0; w2 < 4; w2++) {
                const float* p = pl + t * PLP + w2 * 6;
                sx  += p[0];  sx2 += p[1];
                d0  += p[2];  d1  += p[3];
                d2  += p[4];  d3  += p[5];
            }
            const float mu      = sx * (1.0f / 32.0f);
            const float var     = fmaxf(fmaf(sx2, 1.0f / 32.0f, -mu * mu), 0.0f);
            const float inv_std = rsqrtf(var + LNEPS_C);
            float4 lg;
            lg.x = fmaf(inv_std, fmaf(-mu, Sa4.x, d0), Sb4.x);
            lg.y = fmaf(inv_std, fmaf(-mu, Sa4.y, d1), Sb4.y);
            lg.z = fmaf(inv_std, fmaf(-mu, Sa4.z, d2), Sb4.z);
            lg.w = fmaf(inv_std, fmaf(-mu, Sa4.w, d3), Sb4.w);
            ((float4*)(out_logits + (size_t)bat * TT * CCLS))[tb + t] = lg;
        }
        // next B1 orders smr/pl reuse
    }
}

extern "C" void kernel_launch(void* const* d_in, const int* in_sizes, int n_in,
                              void* d_out, int out_size) {
    const float* z_ticks = (const float*)d_in[0];
    const float* proj    = (const float*)d_in[1];
    const float* ln_w    = (const float*)d_in[2];
    const float* ln_b    = (const float*)d_in[3];
    const float* cls_w   = (const float*)d_in[4];
    const float* cls_b   = (const float*)d_in[5];

    float* out_x      = (float*)d_out;
    float* out_logits = out_x + (size_t)BATCH * TT * DOUTN;

    sync_head_kernel<<<GRID, 128>>>(z_ticks, proj, ln_w, ln_b,
                                    cls_w, cls_b, out_x, out_logits);
}

// round 16
// speedup vs baseline: 1.3234x; 1.0109x over previous
#include <cuda_runtime.h>
#include <cstddef>
#include <cstdint>

#define BATCH 512
#define TT    512
#define DD    128
#define DOUTN 32
#define CCLS  4
#define TBK   32
#define NTILE (TT / TBK)      // 16
#define RP    33
#define PLP   25

#define ALPHA_C 0.1f
#define GAMMA_C 0.9f
#define EPS_C   1e-5f
#define EPSH_C  1e-6f
#define LNEPS_C 1e-5f

__device__ __forceinline__ float warp_sum(float v) {
#pragma unroll
    for (int s = 16; s > 0; s >>= 1)
        v += __shfl_xor_sync(0xffffffffu, v, s, 32);
    return v;
}

__device__ __forceinline__ unsigned long long fma2(unsigned long long a,
                                                   unsigned long long b,
                                                   unsigned long long c) {
    unsigned long long d;
    asm("fma.rn.f32x2 %0, %1, %2, %3;" : "=l"(d) : "l"(a), "l"(b), "l"(c));
    return d;
}

__device__ __forceinline__ unsigned long long add2(unsigned long long a,
                                                   unsigned long long b) {
    unsigned long long d;
    asm("add.rn.f32x2 %0, %1, %2;" : "=l"(d) : "l"(a), "l"(b));
    return d;
}

__device__ __forceinline__ unsigned long long pack2(float lo, float hi) {
    unsigned long long r;
    asm("mov.b64 %0, {%1, %2};" : "=l"(r) : "f"(lo), "f"(hi));
    return r;
}

__device__ __forceinline__ void unpack2(unsigned long long v, float& lo, float& hi) {
    asm("mov.b64 {%0, %1}, %2;" : "=f"(lo), "=f"(hi) : "l"(v));
}

__device__ __forceinline__ uint32_t sm_u32(const void* p) {
    uint32_t a;
    asm("{ .reg .u64 t; cvta.to.shared.u64 t, %1; cvt.u32.u64 %0, t; }"
        : "=r"(a) : "l"(p));
    return a;
}

__device__ __forceinline__ void cpa16(uint32_t dst, const void* src) {
    asm volatile("cp.async.cg.shared.global [%0], [%1], 16;" :: "r"(dst), "l"(src));
}
__device__ __forceinline__ void cpa_commit() {
    asm volatile("cp.async.commit_group;");
}
__device__ __forceinline__ void cpa_wait1() {
    asm volatile("cp.async.wait_group 1;");
}
__device__ __forceinline__ void cpa_wait0() {
    asm volatile("cp.async.wait_group 0;");
}

__global__ __launch_bounds__(128, 2)
void sync_head_kernel(const float* __restrict__ z_ticks,
                      const float* __restrict__ proj,
                      const float* __restrict__ ln_w,
                      const float* __restrict__ ln_b,
                      const float* __restrict__ cls_w,
                      const float* __restrict__ cls_b,
                      float* __restrict__ out_x,
                      float* __restrict__ out_logits) {
    __shared__ __align__(16) float  smz[2][TBK * DD];   // z -> z_tilde (dbl buf)
    __shared__ __align__(16) float2 smnm[TBK * DD];     // (num, M2) packed
    __shared__ float smr[TBK * RP];                     // r -> x
    __shared__ float pci[TBK], pcy[TBK], pcz[TBK], pcw[TBK];
    __shared__ float pl[TBK * PLP];                     // LN partials
    __shared__ __align__(16) float A[DOUTN][CCLS];
    __shared__ float4 SaV, SbV;

    const int tid  = threadIdx.x;
    const int lane = tid & 31;
    const int w    = tid >> 5;
    const int b    = blockIdx.x;

    // ---- folded LN x classifier constants ----
    {
        int j = tid >> 2, c = tid & 3;
        A[j][c] = ln_w[j] * cls_w[c * DOUTN + j];
    }
    if (tid < 2 * CCLS) {
        int c = tid & 3;
        float acc = 0.f;
        if (tid < CCLS) {
            for (int j = 0; j < DOUTN; j++) acc += ln_w[j] * cls_w[c * DOUTN + j];
            ((float*)&SaV)[c] = acc;
        } else {
            for (int j = 0; j < DOUTN; j++) acc += ln_b[j] * cls_w[c * DOUTN + j];
            ((float*)&SbV)[c] = acc + cls_b[c];
        }
    }

    // ---- proj column `lane` fully in registers ----
    unsigned long long q[DD / 2];
#pragma unroll
    for (int i = 0; i < DD / 2; i++) {
        float a  = proj[(2 * i) * DOUTN + lane];
        float bb = proj[(2 * i + 1) * DOUTN + lane];
        q[i] = pack2(a, bb);
    }

    const float gmn = __powf(GAMMA_C, -(float)lane);
    const float gpp = __powf(GAMMA_C,  (float)lane);

    const float4* zg4 = (const float4*)(z_ticks + (size_t)b * TT * DD);
    float* oxb  = out_x + (size_t)b * TT * DOUTN;
    float4* olb = (float4*)(out_logits + (size_t)b * TT * CCLS);

    // ---- prefetch tile 0 ----
    {
        const uint32_t dst0 = sm_u32(&smz[0][0]);
#pragma unroll
        for (int k = 0; k < 8; k++)
            cpa16(dst0 + (tid + 128 * k) * 16, zg4 + tid + 128 * k);
        cpa_commit();
    }
    __syncthreads();
    const float4 Sa4 = SaV;
    const float4 Sb4 = SbV;

    float S1c = 0.f, S2c = 0.f;
    float hc[8];
#pragma unroll
    for (int i = 0; i < 8; i++) hc[i] = 0.f;

#pragma unroll 1
    for (int tile = 0; tile < NTILE; tile++) {
        const int tb  = tile * TBK;
        const int cur = tile & 1;
        const int nxt = cur ^ 1;

        if (tid < TBK) {
            const float tau   = (float)(tb + tid + 1);
            const float denom = fmaxf(tau - 1.0f, 1.0f);
            const float idn   = 1.0f / denom;
            pci[tid] = 1.0f / tau;
            pcy[tid] = (1.0f - ALPHA_C) * idn;
            pcz[tid] = ALPHA_C * idn * (1.0f / 128.0f);
            pcw[tid] = (1.0f - GAMMA_C) / (1.0f - __powf(GAMMA_C, tau));
        }

        if (tile + 1 < NTILE) {
            const uint32_t dstn = sm_u32(&smz[nxt][0]);
            const float4* src = zg4 + (size_t)(tb + TBK) * (DD / 4);
#pragma unroll
            for (int k = 0; k < 8; k++)
                cpa16(dstn + (tid + 128 * k) * 16, src + tid + 128 * k);
            cpa_commit();
            cpa_wait1();
        } else {
            cpa_wait0();
        }
        __syncthreads();      // B1

        // ---- phase 2: prefix scan over t for dim d = tid ----
        {
            const float* zc = smz[cur];
#pragma unroll
            for (int t = 0; t < TBK; t++) {
                const float zz = zc[t * DD + tid];
                S1c += zz;
                S2c = fmaf(zz, zz, S2c);
                const float m = S1c * pci[t];
                smnm[t * DD + tid] = make_float2(zz - m, fmaf(-m, S1c, S2c));
            }
        }
        __syncthreads();      // B2

        // ---- phases 3-5 (warp-local rows t = 8w..8w+7) ----
        {
            float c2v[8], c1v[8];
#pragma unroll
            for (int k = 0; k < 8; k++) {
                const int t = w * 8 + k;
                const float2* row = smnm + t * DD;
                float v = (row[lane].y + row[lane + 32].y) +
                          (row[lane + 64].y + row[lane + 96].y);
                v = warp_sum(v);
                c2v[k] = fmaf(v, pcz[t], EPS_C);
                c1v[k] = pcy[t];
            }
#pragma unroll
            for (int k = 0; k < 8; k++) {
                const int t = w * 8 + k;
                const float4* nm4 = (const float4*)(smnm + t * DD);
                float4 a  = nm4[2 * lane];        // (num,M2) for d = 4l, 4l+1
                float4 b2 = nm4[2 * lane + 1];    // d = 4l+2, 4l+3
                float4 zt;
                zt.x = a.x  * rsqrtf(fmaf(a.y,  c1v[k], c2v[k]));
                zt.y = a.z  * rsqrtf(fmaf(a.w,  c1v[k], c2v[k]));
                zt.z = b2.x * rsqrtf(fmaf(b2.y, c1v[k], c2v[k]));
                zt.w = b2.z * rsqrtf(fmaf(b2.w, c1v[k], c2v[k]));
                ((float4*)(smz[cur] + t * DD))[lane] = zt;
            }
            __syncwarp();
#pragma unroll
            for (int k = 0; k < 8; k++) {
                const int t = w * 8 + k;
                const ulonglong2* zp = (const ulonglong2*)(smz[cur] + t * DD);
                unsigned long long a0 = 0ull, a1 = 0ull, a2 = 0ull, a3 = 0ull;
#pragma unroll
                for (int c = 0; c < 16; c++) {
                    ulonglong2 za = zp[2 * c];
                    ulonglong2 zc = zp[2 * c + 1];
                    a0 = fma2(za.x, q[4 * c + 0], a0);
                    a1 = fma2(za.y, q[4 * c + 1], a1);
                    a2 = fma2(zc.x, q[4 * c + 2], a2);
                    a3 = fma2(zc.y, q[4 * c + 3], a3);
                }
                unsigned long long sT = add2(add2(a0, a1), add2(a2, a3));
                float rlo, rhi;
                unpack2(sT, rlo, rhi);
                smr[t * RP + lane] = rlo + rhi;
            }
        }
        __syncthreads();      // B3

        // ---- phase 6: parallel h prefix-scan (lane = t) + LN partials ----
        {
            const float invs = pcw[lane];
            float sx = 0.f, sx2 = 0.f;
            float d0 = 0.f, d1 = 0.f, d2 = 0.f, d3 = 0.f;
#pragma unroll
            for (int i = 0; i < 8; i++) {
                const int j = w * 8 + i;
                const float r = smr[lane * RP + j];
                float pf = r * r * gmn;
#pragma unroll
                for (int s = 1; s < 32; s <<= 1) {
                    float o = __shfl_up_sync(0xffffffffu, pf, s, 32);
                    if (lane >= s) pf += o;
                }
                const float h = gpp * fmaf(GAMMA_C, hc[i], pf);
                hc[i] = __shfl_sync(0xffffffffu, h, 31, 32);
                const float x = __logf(fmaf(h, invs, EPSH_C));
                smr[lane * RP + j] = x;
                const float4 Aj = *(const float4*)&A[j][0];
                sx  += x;
                sx2 = fmaf(x, x, sx2);
                d0 = fmaf(x, Aj.x, d0);
                d1 = fmaf(x, Aj.y, d1);
                d2 = fmaf(x, Aj.z, d2);
                d3 = fmaf(x, Aj.w, d3);
            }
            float* p = pl + lane * PLP + w * 6;
            p[0] = sx;  p[1] = sx2;
            p[2] = d0;  p[3] = d1;  p[4] = d2;  p[5] = d3;
        }
        __syncthreads();      // B4

        // ---- phase 7a: x store (all threads, coalesced STG.128) ----
        {
#pragma unroll
            for (int it = 0; it < 2; it++) {
                const int g  = tid + 128 * it;
                const int t  = g >> 3;
                const int j0 = (g & 7) * 4;
                float4 v;
                v.x = smr[t * RP + j0 + 0];
                v.y = smr[t * RP + j0 + 1];
                v.z = smr[t * RP + j0 + 2];
                v.w = smr[t * RP + j0 + 3];
                ((float4*)(oxb + (size_t)(tb + t) * DOUTN))[g & 7] = v;
            }
        }
        // ---- phase 7b: LN finish, spread across warps (lane < 8) ----
        if (lane < 8) {
            const int t = w * 8 + lane;
            float sx = 0.f, sx2 = 0.f, d0 = 0.f, d1 = 0.f, d2 = 0.f, d3 = 0.f;
#pragma unroll
            for (int w2 = 0; w2 < 4; w2++) {
                const float* p = pl + t * PLP + w2 * 6;
                sx  += p[0];  sx2 += p[1];
                d0  += p[2];  d1  += p[3];
                d2  += p[4];  d3  += p[5];
            }
            const float mu      = sx * (1.0f / 32.0f);
            const float var     = fmaxf(fmaf(sx2, 1.0f / 32.0f, -mu * mu), 0.0f);
            const float inv_std = rsqrtf(var + LNEPS_C);
            float4 lg;
            lg.x = fmaf(inv_std, fmaf(-mu, Sa4.x, d0), Sb4.x);
            lg.y = fmaf(inv_std, fmaf(-mu, Sa4.y, d1), Sb4.y);
            lg.z = fmaf(inv_std, fmaf(-mu, Sa4.z, d2), Sb4.z);
            lg.w = fmaf(inv_std, fmaf(-mu, Sa4.w, d3), Sb4.w);
            olb[tb + t] = lg;
        }
        // next B1 orders smr/pl reuse
    }
}

extern "C" void kernel_launch(void* const* d_in, const int* in_sizes, int n_in,
                              void* d_out, int out_size) {
    const float* z_ticks = (const float*)d_in[0];
    const float* proj    = (const float*)d_in[1];
    const float* ln_w    = (const float*)d_in[2];
    const float* ln_b    = (const float*)d_in[3];
    const float* cls_w   = (const float*)d_in[4];
    const float* cls_b   = (const float*)d_in[5];

    float* out_x      = (float*)d_out;
    float* out_logits = out_x + (size_t)BATCH * TT * DOUTN;

    sync_head_kernel<<<BATCH, 128>>>(z_ticks, proj, ln_w, ln_b,
                                     cls_w, cls_b, out_x, out_logits);
}

// round 17
// speedup vs baseline: 1.4682x; 1.1094x over previous
#include <cuda_runtime.h>
#include <cstddef>
#include <cstdint>

#define BATCH 512
#define TT    512
#define DD    128
#define DOUTN 32
#define CCLS  4
#define TBK   32
#define NTILE (TT / TBK)
#define RP    33
#define PLP   25

#define ALPHA_C 0.1f
#define GAMMA_C 0.9f
#define EPS_C   1e-5f
#define EPSH_C  1e-6f
#define LNEPS_C 1e-5f

__device__ __forceinline__ float warp_sum(float v) {
#pragma unroll
    for (int s = 16; s > 0; s >>= 1)
        v += __shfl_xor_sync(0xffffffffu, v, s, 32);
    return v;
}

__device__ __forceinline__ unsigned long long fma2(unsigned long long a,
                                                   unsigned long long b,
                                                   unsigned long long c) {
    unsigned long long d;
    asm("fma.rn.f32x2 %0, %1, %2, %3;" : "=l"(d) : "l"(a), "l"(b), "l"(c));
    return d;
}

__device__ __forceinline__ unsigned long long add2(unsigned long long a,
                                                   unsigned long long b) {
    unsigned long long d;
    asm("add.rn.f32x2 %0, %1, %2;" : "=l"(d) : "l"(a), "l"(b));
    return d;
}

__device__ __forceinline__ unsigned long long pack2(float lo, float hi) {
    unsigned long long r;
    asm("mov.b64 %0, {%1, %2};" : "=l"(r) : "f"(lo), "f"(hi));
    return r;
}

__device__ __forceinline__ void unpack2(unsigned long long v, float& lo, float& hi) {
    asm("mov.b64 {%0, %1}, %2;" : "=f"(lo), "=f"(hi) : "l"(v));
}

__device__ __forceinline__ uint32_t sm_u32(const void* p) {
    uint32_t a;
    asm("{ .reg .u64 t; cvta.to.shared.u64 t, %1; cvt.u32.u64 %0, t; }"
        : "=r"(a) : "l"(p));
    return a;
}

__device__ __forceinline__ void cpa16(uint32_t dst, const void* src) {
    asm volatile("cp.async.cg.shared.global [%0], [%1], 16;" :: "r"(dst), "l"(src));
}
__device__ __forceinline__ void cpa_commit() {
    asm volatile("cp.async.commit_group;");
}
__device__ __forceinline__ void cpa_wait1() {
    asm volatile("cp.async.wait_group 1;");
}
__device__ __forceinline__ void cpa_wait0() {
    asm volatile("cp.async.wait_group 0;");
}

__global__ __launch_bounds__(128, 2)
void sync_head_kernel(const float* __restrict__ z_ticks,
                      const float* __restrict__ proj,
                      const float* __restrict__ ln_w,
                      const float* __restrict__ ln_b,
                      const float* __restrict__ cls_w,
                      const float* __restrict__ cls_b,
                      float* __restrict__ out_x,
                      float* __restrict__ out_logits) {
    __shared__ __align__(16) float smz[2][TBK * DD];   // z -> num -> z_tilde
    __shared__ __align__(16) float smM2[TBK * DD];     // M2[t][d]
    __shared__ float smr[TBK * RP];                    // r -> x
    __shared__ float gpci[TT], gpcy[TT], gpcz[TT], gpcw[TT];  // all-t constants
    __shared__ float pl[TBK * PLP];                    // LN partials
    __shared__ __align__(16) float A[DOUTN][CCLS];
    __shared__ float4 SaV, SbV;

    const int tid  = threadIdx.x;
    const int lane = tid & 31;
    const int w    = tid >> 5;
    const int b    = blockIdx.x;

    // ---- all per-t constants, computed ONCE ----
    for (int i = tid; i < TT; i += 128) {
        const float tau   = (float)(i + 1);
        const float denom = fmaxf(tau - 1.0f, 1.0f);
        const float idn   = 1.0f / denom;
        gpci[i] = 1.0f / tau;
        gpcy[i] = (1.0f - ALPHA_C) * idn;
        gpcz[i] = ALPHA_C * idn * (1.0f / 128.0f);
        gpcw[i] = (1.0f - GAMMA_C) / (1.0f - __powf(GAMMA_C, tau));
    }

    // ---- folded LN x classifier constants ----
    {
        int j = tid >> 2, c = tid & 3;
        A[j][c] = ln_w[j] * cls_w[c * DOUTN + j];
    }
    if (tid < 2 * CCLS) {
        int c = tid & 3;
        float acc = 0.f;
        if (tid < CCLS) {
            for (int j = 0; j < DOUTN; j++) acc += ln_w[j] * cls_w[c * DOUTN + j];
            ((float*)&SaV)[c] = acc;
        } else {
            for (int j = 0; j < DOUTN; j++) acc += ln_b[j] * cls_w[c * DOUTN + j];
            ((float*)&SbV)[c] = acc + cls_b[c];
        }
    }

    // ---- proj column `lane` in registers ----
    unsigned long long q[DD / 2];
#pragma unroll
    for (int i = 0; i < DD / 2; i++) {
        float a  = proj[(2 * i) * DOUTN + lane];
        float bb = proj[(2 * i + 1) * DOUTN + lane];
        q[i] = pack2(a, bb);
    }
    const float gmn = __powf(GAMMA_C, -(float)lane);
    const float gpp = __powf(GAMMA_C,  (float)lane);

    const float4* zg4 = (const float4*)(z_ticks + (size_t)b * TT * DD);
    float* oxb  = out_x + (size_t)b * TT * DOUTN;
    float4* olb = (float4*)(out_logits + (size_t)b * TT * CCLS);

    // ---- prefetch tile 0 ----
    {
        const uint32_t dst0 = sm_u32(&smz[0][0]);
#pragma unroll
        for (int k = 0; k < 8; k++)
            cpa16(dst0 + (tid + 128 * k) * 16, zg4 + tid + 128 * k);
        cpa_commit();
    }
    __syncthreads();
    const float4 Sa4 = SaV;
    const float4 Sb4 = SbV;

    float S1c = 0.f, S2c = 0.f;
    float hc[8];
#pragma unroll
    for (int i = 0; i < 8; i++) hc[i] = 0.f;

#pragma unroll 1
    for (int tile = 0; tile < NTILE; tile++) {
        const int tb  = tile * TBK;
        const int cur = tile & 1;
        const int nxt = cur ^ 1;

        if (tile + 1 < NTILE) {
            const uint32_t dstn = sm_u32(&smz[nxt][0]);
            const float4* src = zg4 + (size_t)(tb + TBK) * (DD / 4);
#pragma unroll
            for (int k = 0; k < 8; k++)
                cpa16(dstn + (tid + 128 * k) * 16, src + tid + 128 * k);
            cpa_commit();
            cpa_wait1();
        } else {
            cpa_wait0();
        }
        __syncthreads();      // B1

        // ---- phase 2: prefix scan over t for dim d = tid ----
        {
            float* zc = smz[cur];
#pragma unroll
            for (int t = 0; t < TBK; t++) {
                const float zz = zc[t * DD + tid];
                S1c += zz;
                S2c = fmaf(zz, zz, S2c);
                const float m   = S1c * gpci[tb + t];
                zc[t * DD + tid]   = zz - m;
                smM2[t * DD + tid] = fmaf(-m, S1c, S2c);
            }
        }
        __syncthreads();      // B2

        // ---- phases 3-5 (warp-local rows t = 8w..8w+7) ----
        {
            float c2v[8], c1v[8];
#pragma unroll
            for (int k = 0; k < 8; k++) {
                const int t = w * 8 + k;
                const float4 m4 = ((const float4*)(smM2 + t * DD))[lane];
                float v = (m4.x + m4.y) + (m4.z + m4.w);
                v = warp_sum(v);
                c2v[k] = fmaf(v, gpcz[tb + t], EPS_C);
                c1v[k] = gpcy[tb + t];
            }
#pragma unroll
            for (int k = 0; k < 8; k++) {
                const int t = w * 8 + k;
                float4* zrow  = (float4*)(smz[cur] + t * DD);
                float4* m2row = (float4*)(smM2 + t * DD);
                float4 nm = zrow[lane];
                float4 m2 = m2row[lane];
                float4 zt;
                zt.x = nm.x * rsqrtf(fmaf(m2.x, c1v[k], c2v[k]));
                zt.y = nm.y * rsqrtf(fmaf(m2.y, c1v[k], c2v[k]));
                zt.z = nm.z * rsqrtf(fmaf(m2.z, c1v[k], c2v[k]));
                zt.w = nm.w * rsqrtf(fmaf(m2.w, c1v[k], c2v[k]));
                zrow[lane] = zt;
            }
            __syncwarp();
#pragma unroll
            for (int k = 0; k < 8; k++) {
                const int t = w * 8 + k;
                const ulonglong2* zp = (const ulonglong2*)(smz[cur] + t * DD);
                unsigned long long a0 = 0ull, a1 = 0ull, a2 = 0ull, a3 = 0ull;
#pragma unroll
                for (int c = 0; c < 16; c++) {
                    ulonglong2 za = zp[2 * c];
                    ulonglong2 zc = zp[2 * c + 1];
                    a0 = fma2(za.x, q[4 * c + 0], a0);
                    a1 = fma2(za.y, q[4 * c + 1], a1);
                    a2 = fma2(zc.x, q[4 * c + 2], a2);
                    a3 = fma2(zc.y, q[4 * c + 3], a3);
                }
                unsigned long long sT = add2(add2(a0, a1), add2(a2, a3));
                float rlo, rhi;
                unpack2(sT, rlo, rhi);
                smr[t * RP + lane] = rlo + rhi;
            }
        }
        __syncthreads();      // B3

        // ---- phase 6: parallel h prefix-scan (lane = t) + LN partials ----
        {
            const float invs = gpcw[tb + lane];
            float sx = 0.f, sx2 = 0.f;
            float d0 = 0.f, d1 = 0.f, d2 = 0.f, d3 = 0.f;
#pragma unroll
            for (int i = 0; i < 8; i++) {
                const int j = w * 8 + i;
                const float r = smr[lane * RP + j];
                float pf = r * r * gmn;
#pragma unroll
                for (int s = 1; s < 32; s <<= 1) {
                    float o = __shfl_up_sync(0xffffffffu, pf, s, 32);
                    if (lane >= s) pf += o;
                }
                const float h = gpp * fmaf(GAMMA_C, hc[i], pf);
                hc[i] = __shfl_sync(0xffffffffu, h, 31, 32);
                const float x = __logf(fmaf(h, invs, EPSH_C));
                smr[lane * RP + j] = x;
                const float4 Aj = *(const float4*)&A[j][0];
                sx  += x;
                sx2 = fmaf(x, x, sx2);
                d0 = fmaf(x, Aj.x, d0);
                d1 = fmaf(x, Aj.y, d1);
                d2 = fmaf(x, Aj.z, d2);
                d3 = fmaf(x, Aj.w, d3);
            }
            float* p = pl + lane * PLP + w * 6;
            p[0] = sx;  p[1] = sx2;
            p[2] = d0;  p[3] = d1;  p[4] = d2;  p[5] = d3;
        }
        __syncthreads();      // B4

        // ---- phase 7a: x store (all threads, coalesced STG.128) ----
        {
#pragma unroll
            for (int it = 0; it < 2; it++) {
                const int g  = tid + 128 * it;
                const int t  = g >> 3;
                const int j0 = (g & 7) * 4;
                float4 v;
                v.x = smr[t * RP + j0 + 0];
                v.y = smr[t * RP + j0 + 1];
                v.z = smr[t * RP + j0 + 2];
                v.w = smr[t * RP + j0 + 3];
                ((float4*)(oxb + (size_t)(tb + t) * DOUTN))[g & 7] = v;
            }
        }
        // ---- phase 7b: LN finish, spread across warps (lane < 8) ----
        if (lane < 8) {
            const int t = w * 8 + lane;
            float sx = 0.f, sx2 = 0.f, d0 = 0.f, d1 = 0.f, d2 = 0.f, d3 = 0.f;
#pragma unroll
            for (int w2 = 0; w2 < 4; w2++) {
                const float* p = pl + t * PLP + w2 * 6;
                sx  += p[0];  sx2 += p[1];
                d0  += p[2];  d1  += p[3];
                d2  += p[4];  d3  += p[5];
            }
            const float mu      = sx * (1.0f / 32.0f);
            const float var     = fmaxf(fmaf(sx2, 1.0f / 32.0f, -mu * mu), 0.0f);
            const float inv_std = rsqrtf(var + LNEPS_C);
            float4 lg;
            lg.x = fmaf(inv_std, fmaf(-mu, Sa4.x, d0), Sb4.x);
            lg.y = fmaf(inv_std, fmaf(-mu, Sa4.y, d1), Sb4.y);
            lg.z = fmaf(inv_std, fmaf(-mu, Sa4.z, d2), Sb4.z);
            lg.w = fmaf(inv_std, fmaf(-mu, Sa4.w, d3), Sb4.w);
            olb[tb + t] = lg;
        }
        // next B1 orders smr/pl reuse
    }
}

extern "C" void kernel_launch(void* const* d_in, const int* in_sizes, int n_in,
                              void* d_out, int out_size) {
    const float* z_ticks = (const float*)d_in[0];
    const float* proj    = (const float*)d_in[1];
    const float* ln_w    = (const float*)d_in[2];
    const float* ln_b    = (const float*)d_in[3];
    const float* cls_w   = (const float*)d_in[4];
    const float* cls_b   = (const float*)d_in[5];

    float* out_x      = (float*)d_out;
    float* out_logits = out_x + (size_t)BATCH * TT * DOUTN;

    sync_head_kernel<<<BATCH, 128>>>(z_ticks, proj, ln_w, ln_b,
                                     cls_w, cls_b, out_x, out_logits);
}